// round 8
// baseline (speedup 1.0000x reference)
#include <cuda_runtime.h>

// Problem constants
#define BN     8
#define DD     64
#define NN     3136        // H*W
#define KK     32
#define TPB    1024        // 32 warps -> 8 per SMSP (2x latency hiding)
#define ITEMS  3           // 1024*3 = 3072 of 3136
#define REMOFF 3072        // 64-elem row tail, handled by warps 0-7
#define NBLK   128         // persistent, 1 block/SM, all resident
#define RPB    4           // rows per block: 128*4 = 512 = B*D

typedef unsigned long long ull;

__device__ float    g_EM[BN * DD];
__device__ unsigned g_count = 0;    // monotonic epoch barrier (graph-replay safe)

__device__ __forceinline__ float ex2f(float x) {
    float r;
    asm("ex2.approx.ftz.f32 %0, %1;" : "=f"(r) : "f"(x));
    return r;
}
__device__ __forceinline__ ull pack2(float lo, float hi) {
    ull r;
    asm("mov.b64 %0, {%1, %2};" : "=l"(r) : "f"(lo), "f"(hi));
    return r;
}
__device__ __forceinline__ void unpack2(ull v, float& lo, float& hi) {
    asm("mov.b64 {%0, %1}, %2;" : "=f"(lo), "=f"(hi) : "l"(v));
}
__device__ __forceinline__ ull fma2(ull a, ull b, ull c) {
    ull r;
    asm("fma.rn.f32x2 %0, %1, %2, %3;" : "=l"(r) : "l"(a), "l"(b), "l"(c));
    return r;
}
__device__ __forceinline__ ull add2(ull a, ull b) {
    ull r;
    asm("add.rn.f32x2 %0, %1, %2;" : "=l"(r) : "l"(a), "l"(b));
    return r;
}
__device__ __forceinline__ unsigned ld_acquire(const unsigned* p) {
    unsigned v;
    asm volatile("ld.global.acquire.gpu.u32 %0, [%1];" : "=r"(v) : "l"(p));
    return v;
}
__device__ __forceinline__ float ldcg_f(const float* p) {
    float v;
    asm volatile("ld.global.cg.f32 %0, [%1];" : "=f"(v) : "l"(p));
    return v;
}

__global__ __launch_bounds__(TPB, 1)
void enc_fused(const float* __restrict__ X,
               const float* __restrict__ codewords,
               const float* __restrict__ scale,
               const float* __restrict__ fc_w,
               const float* __restrict__ fc_b,
               float* __restrict__ out)
{
    __shared__ ulonglong2 cAB[RPB][KK];   // {(a,a),(b,b)} packed
    __shared__ ulonglong2 cCW[RPB][KK];   // {(c,c),(cw,cw)} packed
    __shared__ float4     cS[RPB][KK];    // scalar (a,b,c,cw) for item2 + tail
    __shared__ float      wsum[2][TPB / 32];
    __shared__ float      tsum[8];        // tail partial sums (one per tail warp)
    __shared__ float      sEM[DD];
    __shared__ float      sG[RPB];

    const int tid  = threadIdx.x;
    const int wid  = tid >> 5;
    const int lane = tid & 31;
    const int bd0  = blockIdx.x * RPB;    // 4 consecutive bd, same b
    const int b    = bd0 >> 6;

    // ---- preload all 4 rows' constants once ----
    if (tid < RPB * KK) {
        const int r = tid >> 5, k = tid & 31;
        const int d = (bd0 + r) & (DD - 1);
        const float L2E = 1.4426950408889634f;
        float s  = scale[k * DD + d] * L2E;
        float c  = codewords[k * DD + d];
        float bb = -2.0f * s * c;
        float cc = s * c * c;
        cAB[r][k] = make_ulonglong2(pack2(s, s),  pack2(bb, bb));
        cCW[r][k] = make_ulonglong2(pack2(cc, cc), pack2(c, c));
        cS[r][k]  = make_float4(s, bb, cc, c);
    }

    // ---- row-0 X loads (issued before the sync to overlap) ----
    float xs[ITEMS];
    {
        const float* xr = X + (size_t)bd0 * NN;
        #pragma unroll
        for (int i = 0; i < ITEMS; i++) xs[i] = xr[tid + i * TPB];
    }
    // tail element: warps 0-7 own row (wid>>1), half (wid&1)
    float xrem = 0.0f;
    const int trow = wid >> 1;
    const int tcol = REMOFF + (wid & 1) * 32 + lane;
    if (wid < 8) xrem = X[(size_t)(bd0 + trow) * NN + tcol];

    __syncthreads();

    // ---- tail pass: 8 warps, one 32-k scalar loop each ----
    float Erem = 0.0f;
    if (wid < 8) {
        float se = 0.0f, sc_ = 0.0f;
        #pragma unroll 4
        for (int k = 0; k < KK; k++) {
            float4 q = cS[trow][k];
            float t = fmaf(fmaf(q.x, xrem, q.y), xrem, q.z);
            float e = ex2f(t);
            se += e;
            sc_ = fmaf(e, q.w, sc_);
        }
        Erem = xrem - __fdividef(sc_, se);
        float rs = Erem;
        #pragma unroll
        for (int off = 16; off; off >>= 1)
            rs += __shfl_xor_sync(0xffffffffu, rs, off);
        if (lane == 0) tsum[wid] = rs;
    }

    // ---- main rows: pair (items 0,1) in f32x2 + item 2 scalar ----
    float Ereg[RPB][ITEMS];

    #pragma unroll
    for (int r = 0; r < RPB; r++) {
        const int bd = bd0 + r;

        // prefetch next row behind this row's k-loop
        float xn[ITEMS];
        const bool more = (r + 1 < RPB);
        if (more) {
            const float* xr = X + (size_t)(bd + 1) * NN;
            #pragma unroll
            for (int i = 0; i < ITEMS; i++) xn[i] = xr[tid + i * TPB];
        }

        const ull x2 = pack2(xs[0], xs[1]);
        const float x1 = xs[2];
        ull   se2 = 0ull, sc2 = 0ull;
        float seS = 0.0f, scS = 0.0f;

        #pragma unroll 4
        for (int k = 0; k < KK; k++) {
            ulonglong2 qab = cAB[r][k];
            ulonglong2 qcw = cCW[r][k];
            float4     qs  = cS[r][k];
            // packed pair
            ull t2 = fma2(fma2(qab.x, x2, qab.y), x2, qcw.x);
            float tl, th; unpack2(t2, tl, th);
            ull e2 = pack2(ex2f(tl), ex2f(th));
            se2 = add2(se2, e2);
            sc2 = fma2(e2, qcw.y, sc2);
            // scalar item
            float t = fmaf(fmaf(qs.x, x1, qs.y), x1, qs.z);
            float e = ex2f(t);
            seS += e;
            scS = fmaf(e, qs.w, scS);
        }

        float sel, seh, scl, sch;
        unpack2(se2, sel, seh);
        unpack2(sc2, scl, sch);
        float E0 = xs[0] - __fdividef(scl, sel);
        float E1 = xs[1] - __fdividef(sch, seh);
        float E2 = x1    - __fdividef(scS, seS);
        Ereg[r][0] = E0; Ereg[r][1] = E1; Ereg[r][2] = E2;

        float esum = E0 + E1 + E2;
        #pragma unroll
        for (int off = 16; off; off >>= 1)
            esum += __shfl_xor_sync(0xffffffffu, esum, off);
        if (lane == 0) wsum[r & 1][wid] = esum;
        __syncthreads();
        if (tid < 32) {
            float s = wsum[r & 1][lane];
            #pragma unroll
            for (int off = 16; off; off >>= 1)
                s += __shfl_xor_sync(0xffffffffu, s, off);
            if (lane == 0)
                g_EM[bd] = (s + tsum[2 * r] + tsum[2 * r + 1]) * (1.0f / KK);
        }

        if (more) {
            #pragma unroll
            for (int i = 0; i < ITEMS; i++) xs[i] = xn[i];
        }
    }

    // ---- grid barrier (128 blocks, all resident; monotonic epoch) ----
    __threadfence();
    __syncthreads();
    if (tid == 0) {
        unsigned old = atomicAdd(&g_count, 1u);
        unsigned target = (old / NBLK + 1u) * NBLK;
        while (ld_acquire(&g_count) < target)
            __nanosleep(64);
    }
    __syncthreads();

    // ---- gamma for this block's 4 rows (same b) ----
    if (tid < DD) sEM[tid] = ldcg_f(&g_EM[b * DD + tid]);
    __syncthreads();
    if (tid < RPB) {
        const int d = (bd0 + tid) & (DD - 1);
        float acc = fc_b[d];
        const float* wrow = fc_w + d * DD;
        #pragma unroll
        for (int i = 0; i < DD; i++)
            acc = fmaf(sEM[i], wrow[i], acc);
        sG[tid] = 1.0f + 1.0f / (1.0f + __expf(-acc));   // 1 + sigmoid
    }
    __syncthreads();

    // ---- final: out = relu(E * (1 + gamma)) ----
    #pragma unroll
    for (int r = 0; r < RPB; r++) {
        const float g = sG[r];
        float* ob = out + (size_t)(bd0 + r) * NN;
        #pragma unroll
        for (int i = 0; i < ITEMS; i++) {
            float v = Ereg[r][i] * g;
            ob[tid + i * TPB] = v > 0.0f ? v : 0.0f;
        }
    }
    if (wid < 8) {
        float v = Erem * sG[trow];
        out[(size_t)(bd0 + trow) * NN + tcol] = v > 0.0f ? v : 0.0f;
    }
}

extern "C" void kernel_launch(void* const* d_in, const int* in_sizes, int n_in,
                              void* d_out, int out_size)
{
    const float* X  = (const float*)d_in[0];
    const float* cw = (const float*)d_in[1];
    const float* sc = (const float*)d_in[2];
    const float* fw = (const float*)d_in[3];
    const float* fb = (const float*)d_in[4];
    float* out = (float*)d_out;

    enc_fused<<<NBLK, TPB>>>(X, cw, sc, fw, fb, out);
}

// round 9
// speedup vs baseline: 1.2048x; 1.2048x over previous
#include <cuda_runtime.h>

// Problem constants
#define BN     8
#define DD     64
#define NN     3136        // H*W
#define KK     32
#define TPB    768         // 24 warps -> 6 per SMSP (reg cap 84, no spills)
#define NPAIR  2           // 2 f32x2 pairs = 4 items; 768*4 = 3072
#define REMOFF 3072        // 64-elem row tail, handled by warps 0-7
#define NBLK   128         // persistent, 1 block/SM, all resident
#define RPB    4           // rows per block: 128*4 = 512 = B*D
#define NW     (TPB / 32)  // 24 warps

typedef unsigned long long ull;

__device__ float    g_EM[BN * DD];
__device__ unsigned g_count = 0;    // monotonic epoch barrier (graph-replay safe)

__device__ __forceinline__ float ex2f(float x) {
    float r;
    asm("ex2.approx.ftz.f32 %0, %1;" : "=f"(r) : "f"(x));
    return r;
}
__device__ __forceinline__ ull pack2(float lo, float hi) {
    ull r;
    asm("mov.b64 %0, {%1, %2};" : "=l"(r) : "f"(lo), "f"(hi));
    return r;
}
__device__ __forceinline__ void unpack2(ull v, float& lo, float& hi) {
    asm("mov.b64 {%0, %1}, %2;" : "=f"(lo), "=f"(hi) : "l"(v));
}
__device__ __forceinline__ ull fma2(ull a, ull b, ull c) {
    ull r;
    asm("fma.rn.f32x2 %0, %1, %2, %3;" : "=l"(r) : "l"(a), "l"(b), "l"(c));
    return r;
}
__device__ __forceinline__ ull add2(ull a, ull b) {
    ull r;
    asm("add.rn.f32x2 %0, %1, %2;" : "=l"(r) : "l"(a), "l"(b));
    return r;
}
__device__ __forceinline__ unsigned ld_acquire(const unsigned* p) {
    unsigned v;
    asm volatile("ld.global.acquire.gpu.u32 %0, [%1];" : "=r"(v) : "l"(p));
    return v;
}
__device__ __forceinline__ float ldcg_f(const float* p) {
    float v;
    asm volatile("ld.global.cg.f32 %0, [%1];" : "=f"(v) : "l"(p));
    return v;
}

__global__ __launch_bounds__(TPB, 1)
void enc_fused(const float* __restrict__ X,
               const float* __restrict__ codewords,
               const float* __restrict__ scale,
               const float* __restrict__ fc_w,
               const float* __restrict__ fc_b,
               float* __restrict__ out)
{
    __shared__ ulonglong2 cAB[RPB][KK];   // {(a,a),(b,b)} packed
    __shared__ ulonglong2 cCW[RPB][KK];   // {(c,c),(cw,cw)} packed
    __shared__ float      wsum[2][NW];
    __shared__ float      tsum[8];        // tail partial sums
    __shared__ float      sEM[DD];
    __shared__ float      sG[RPB];

    const int tid  = threadIdx.x;
    const int wid  = tid >> 5;
    const int lane = tid & 31;
    const int bd0  = blockIdx.x * RPB;    // 4 consecutive bd, same b
    const int b    = bd0 >> 6;

    // ---- preload all 4 rows' packed constants once ----
    if (tid < RPB * KK) {
        const int r = tid >> 5, k = tid & 31;
        const int d = (bd0 + r) & (DD - 1);
        const float L2E = 1.4426950408889634f;
        float s  = scale[k * DD + d] * L2E;
        float c  = codewords[k * DD + d];
        float bb = -2.0f * s * c;
        float cc = s * c * c;
        cAB[r][k] = make_ulonglong2(pack2(s, s),   pack2(bb, bb));
        cCW[r][k] = make_ulonglong2(pack2(cc, cc), pack2(c, c));
    }

    // ---- row-0 X loads: pairs at float2 index (tid + p*TPB) ----
    ull x2c[NPAIR];
    {
        const float2* xr = (const float2*)(X + (size_t)bd0 * NN);
        #pragma unroll
        for (int p = 0; p < NPAIR; p++) {
            float2 v = xr[tid + p * TPB];
            x2c[p] = pack2(v.x, v.y);
        }
    }
    // tail element: warps 0-7 own row (wid>>1), half (wid&1)
    float xrem = 0.0f;
    const int trow = wid >> 1;
    const int tcol = REMOFF + (wid & 1) * 32 + lane;
    if (wid < 8) xrem = X[(size_t)(bd0 + trow) * NN + tcol];

    __syncthreads();

    // ---- tail pass: 8 warps (2 per SMSP), one 32-k loop each ----
    float Erem = 0.0f;
    if (wid < 8) {
        float se = 0.0f, sc_ = 0.0f;
        #pragma unroll 4
        for (int k = 0; k < KK; k++) {
            ulonglong2 qab = cAB[trow][k];
            ulonglong2 qcw = cCW[trow][k];
            float a, bb, cc, cw, dmy;
            unpack2(qab.x, a, dmy);
            unpack2(qab.y, bb, dmy);
            unpack2(qcw.x, cc, dmy);
            unpack2(qcw.y, cw, dmy);
            float t = fmaf(fmaf(a, xrem, bb), xrem, cc);
            float e = ex2f(t);
            se += e;
            sc_ = fmaf(e, cw, sc_);
        }
        Erem = xrem - __fdividef(sc_, se);
        float rs = Erem;
        #pragma unroll
        for (int off = 16; off; off >>= 1)
            rs += __shfl_xor_sync(0xffffffffu, rs, off);
        if (lane == 0) tsum[wid] = rs;
    }

    // ---- main rows: pure f32x2, 2 pairs/thread ----
    float Ereg[RPB][2 * NPAIR];

    #pragma unroll
    for (int r = 0; r < RPB; r++) {
        const int bd = bd0 + r;

        // prefetch next row behind this row's k-loop
        ull x2n[NPAIR];
        const bool more = (r + 1 < RPB);
        if (more) {
            const float2* xr = (const float2*)(X + (size_t)(bd + 1) * NN);
            #pragma unroll
            for (int p = 0; p < NPAIR; p++) {
                float2 v = xr[tid + p * TPB];
                x2n[p] = pack2(v.x, v.y);
            }
        }

        ull se2[NPAIR], sc2[NPAIR];
        #pragma unroll
        for (int p = 0; p < NPAIR; p++) { se2[p] = 0ull; sc2[p] = 0ull; }

        #pragma unroll 4
        for (int k = 0; k < KK; k++) {
            ulonglong2 qab = cAB[r][k];
            ulonglong2 qcw = cCW[r][k];
            #pragma unroll
            for (int p = 0; p < NPAIR; p++) {
                ull t2 = fma2(fma2(qab.x, x2c[p], qab.y), x2c[p], qcw.x);
                float tl, th; unpack2(t2, tl, th);
                ull e2 = pack2(ex2f(tl), ex2f(th));
                se2[p] = add2(se2[p], e2);
                sc2[p] = fma2(e2, qcw.y, sc2[p]);
            }
        }

        float esum = 0.0f;
        #pragma unroll
        for (int p = 0; p < NPAIR; p++) {
            float sel, seh, scl, sch, xl, xh;
            unpack2(se2[p], sel, seh);
            unpack2(sc2[p], scl, sch);
            unpack2(x2c[p], xl, xh);
            float El = xl - __fdividef(scl, sel);
            float Eh = xh - __fdividef(sch, seh);
            Ereg[r][2 * p]     = El;
            Ereg[r][2 * p + 1] = Eh;
            esum += El + Eh;
        }

        #pragma unroll
        for (int off = 16; off; off >>= 1)
            esum += __shfl_xor_sync(0xffffffffu, esum, off);
        if (lane == 0) wsum[r & 1][wid] = esum;
        __syncthreads();
        if (tid < 32) {
            float s = (lane < NW) ? wsum[r & 1][lane] : 0.0f;
            #pragma unroll
            for (int off = 16; off; off >>= 1)
                s += __shfl_xor_sync(0xffffffffu, s, off);
            if (lane == 0)
                g_EM[bd] = (s + tsum[2 * r] + tsum[2 * r + 1]) * (1.0f / KK);
        }

        if (more) {
            #pragma unroll
            for (int p = 0; p < NPAIR; p++) x2c[p] = x2n[p];
        }
    }

    // ---- grid barrier (128 blocks, all resident; monotonic epoch) ----
    __threadfence();
    __syncthreads();
    if (tid == 0) {
        unsigned old = atomicAdd(&g_count, 1u);
        unsigned target = (old / NBLK + 1u) * NBLK;
        while (ld_acquire(&g_count) < target)
            __nanosleep(64);
    }
    __syncthreads();

    // ---- gamma for this block's 4 rows (same b) ----
    if (tid < DD) sEM[tid] = ldcg_f(&g_EM[b * DD + tid]);
    __syncthreads();
    if (tid < RPB) {
        const int d = (bd0 + tid) & (DD - 1);
        float acc = fc_b[d];
        const float* wrow = fc_w + d * DD;
        #pragma unroll
        for (int i = 0; i < DD; i++)
            acc = fmaf(sEM[i], wrow[i], acc);
        sG[tid] = 1.0f + 1.0f / (1.0f + __expf(-acc));   // 1 + sigmoid
    }
    __syncthreads();

    // ---- final: out = relu(E * (1 + gamma)), STG.64 pairs ----
    #pragma unroll
    for (int r = 0; r < RPB; r++) {
        const float g = sG[r];
        float2* ob = (float2*)(out + (size_t)(bd0 + r) * NN);
        #pragma unroll
        for (int p = 0; p < NPAIR; p++) {
            float vx = Ereg[r][2 * p]     * g;
            float vy = Ereg[r][2 * p + 1] * g;
            float2 v;
            v.x = vx > 0.0f ? vx : 0.0f;
            v.y = vy > 0.0f ? vy : 0.0f;
            ob[tid + p * TPB] = v;
        }
    }
    if (wid < 8) {
        float v = Erem * sG[trow];
        out[(size_t)(bd0 + trow) * NN + tcol] = v > 0.0f ? v : 0.0f;
    }
}

extern "C" void kernel_launch(void* const* d_in, const int* in_sizes, int n_in,
                              void* d_out, int out_size)
{
    const float* X  = (const float*)d_in[0];
    const float* cw = (const float*)d_in[1];
    const float* sc = (const float*)d_in[2];
    const float* fw = (const float*)d_in[3];
    const float* fb = (const float*)d_in[4];
    float* out = (float*)d_out;

    enc_fused<<<NBLK, TPB>>>(X, cw, sc, fw, fb, out);
}